// round 1
// baseline (speedup 1.0000x reference)
#include <cuda_runtime.h>
#include <math.h>

// Problem constants
#define Bb   4
#define Ssz  4096
#define Dd   2048
#define DFFz 8192
#define KSEL 512
#define MROWS (Bb*KSEL)   // 2048 selected rows total

// ---------------- scratch (device globals; no runtime allocation) ----------
__device__ float g_logits[Bb*Ssz];
__device__ int   g_tokens[MROWS];
__device__ float g_rw[MROWS];
__device__ float g_fx[(size_t)MROWS*Dd];        // 16 MB
__device__ float g_h [(size_t)MROWS*DFFz];      // 64 MB

// ---------------- helpers ---------------------------------------------------
__device__ __forceinline__ unsigned int fmono(float f){
    unsigned int b = __float_as_uint(f);
    return (b & 0x80000000u) ? ~b : (b | 0x80000000u);
}
__device__ __forceinline__ unsigned long long pack2(float lo, float hi){
    unsigned long long r;
    asm("mov.b64 %0, {%1, %2};" : "=l"(r) : "f"(lo), "f"(hi));
    return r;
}
__device__ __forceinline__ void ffma2(unsigned long long &c, unsigned long long a, unsigned long long b){
    asm("fma.rn.f32x2 %0, %1, %2, %0;" : "+l"(c) : "l"(a), "l"(b));
}
__device__ __forceinline__ float2 unpack2(unsigned long long v){
    float lo, hi;
    asm("mov.b64 {%0, %1}, %2;" : "=f"(lo), "=f"(hi) : "l"(v));
    return make_float2(lo, hi);
}
__device__ __forceinline__ float gelu_exact(float z){
    return 0.5f * z * (1.0f + erff(z * 0.70710678118654752f));
}

// ---------------- router: logits[b,s] = x[b,s,:].Wr + br --------------------
__global__ void router_kernel(const float* __restrict__ x,
                              const float* __restrict__ Wr,
                              const float* __restrict__ br){
    int row  = blockIdx.x * (blockDim.x >> 5) + (threadIdx.x >> 5);
    int lane = threadIdx.x & 31;
    const float4* xr = reinterpret_cast<const float4*>(x + (size_t)row * Dd);
    const float4* w4 = reinterpret_cast<const float4*>(Wr);
    float s = 0.f;
    #pragma unroll 4
    for (int i = lane; i < Dd/4; i += 32){
        float4 a = xr[i], w = w4[i];
        s += a.x*w.x + a.y*w.y + a.z*w.z + a.w*w.w;
    }
    #pragma unroll
    for (int o = 16; o > 0; o >>= 1) s += __shfl_down_sync(0xffffffffu, s, o);
    if (lane == 0) g_logits[row] = s + br[0];
}

// ---------------- top-k via per-batch bitonic sort --------------------------
// key = (monotone(float) << 32) | ~index : ascending sort puts largest value
// (ties: smallest index) at the end — matches jax.lax.top_k semantics.
__global__ void topk_kernel(){
    __shared__ unsigned long long keys[Ssz];
    __shared__ float sval[KSEL];
    __shared__ int   sidx[KSEL];
    __shared__ float red [KSEL];
    int b   = blockIdx.x;
    int tid = threadIdx.x;           // 1024 threads

    for (int s = tid; s < Ssz; s += blockDim.x){
        unsigned int m = fmono(g_logits[b*Ssz + s]);
        keys[s] = ((unsigned long long)m << 32) | (unsigned int)(~(unsigned int)s);
    }
    __syncthreads();

    for (int k = 2; k <= Ssz; k <<= 1){
        for (int j = k >> 1; j > 0; j >>= 1){
            for (int t = tid; t < Ssz; t += blockDim.x){
                int ixj = t ^ j;
                if (ixj > t){
                    bool up = ((t & k) == 0);
                    unsigned long long a = keys[t], c = keys[ixj];
                    bool sw = up ? (a > c) : (a < c);
                    if (sw){ keys[t] = c; keys[ixj] = a; }
                }
            }
            __syncthreads();
        }
    }

    if (tid < KSEL){
        unsigned long long key = keys[Ssz - 1 - tid];   // tid=0 -> largest
        unsigned int u = (unsigned int)(key >> 32);
        float v = (u & 0x80000000u) ? __uint_as_float(u & 0x7FFFFFFFu)
                                    : __uint_as_float(~u);
        sval[tid] = v;
        sidx[tid] = (int)(~(unsigned int)key);
    }
    __syncthreads();
    float vmax = sval[0];
    if (tid < KSEL) red[tid] = expf(sval[tid] - vmax);
    __syncthreads();
    for (int st = KSEL/2; st > 0; st >>= 1){
        if (tid < st) red[tid] += red[tid + st];
        __syncthreads();
    }
    float denom = red[0];
    if (tid < KSEL){
        g_tokens[b*KSEL + tid] = sidx[tid];
        g_rw   [b*KSEL + tid] = expf(sval[tid] - vmax) / denom;
    }
}

// ---------------- gather selected rows into FX ------------------------------
__global__ void gather_kernel(const float* __restrict__ x){
    int m = blockIdx.x;                   // 0..2047
    int b = m >> 9;
    int t = g_tokens[m];
    const float4* src = reinterpret_cast<const float4*>(x + ((size_t)b*Ssz + t) * Dd);
    float4*       dst = reinterpret_cast<float4*>(g_fx + (size_t)m * Dd);
    for (int i = threadIdx.x; i < Dd/4; i += blockDim.x) dst[i] = src[i];
}

// ---------------- fused GEMM (f32x2 packed FFMA) ----------------------------
// EPI==1: H = gelu(FX @ W1 + b1)            (A=g_fx, C=g_h)
// EPI==2: out[b,t,:] = x[b,t,:] + rw*(H@W2 + b2)   (A=g_h, scatter rows)
template<int EPI>
__global__ __launch_bounds__(256, 2)
void gemm_kernel(const float* __restrict__ Bw, const float* __restrict__ bias,
                 const float* __restrict__ xin, float* __restrict__ out,
                 int N, int K)
{
    const float* A = (EPI == 1) ? g_fx : g_h;
    __shared__ float As[2][16][132];   // transposed A tile, padded
    __shared__ float Bs[2][16][128];

    const int tid = threadIdx.x;
    const int bn = blockIdx.x, bm = blockIdx.y;
    const int tx = tid & 15, ty = tid >> 4;

    const float* Ag = A  + (size_t)(bm * 128) * K;
    const float* Bg = Bw + (size_t)(bn * 128);

    unsigned long long acc[8][4];
    #pragma unroll
    for (int i = 0; i < 8; i++)
        #pragma unroll
        for (int j = 0; j < 4; j++) acc[i][j] = 0ull;

    float4 ra[2], rb[2];
    const int KT = K / 16;

    auto ldA = [&](int kt){
        #pragma unroll
        for (int s = 0; s < 2; s++){
            int f = tid + s*256; int r = f >> 2, c = (f & 3) * 4;
            ra[s] = *reinterpret_cast<const float4*>(Ag + (size_t)r*K + kt*16 + c);
        }
    };
    auto ldB = [&](int kt){
        #pragma unroll
        for (int s = 0; s < 2; s++){
            int f = tid + s*256; int r = f >> 5, c = (f & 31) * 4;
            rb[s] = *reinterpret_cast<const float4*>(Bg + (size_t)(kt*16 + r)*N + c);
        }
    };
    auto stA = [&](int buf){
        #pragma unroll
        for (int s = 0; s < 2; s++){
            int f = tid + s*256; int r = f >> 2, c = (f & 3) * 4;
            As[buf][c+0][r] = ra[s].x; As[buf][c+1][r] = ra[s].y;
            As[buf][c+2][r] = ra[s].z; As[buf][c+3][r] = ra[s].w;
        }
    };
    auto stB = [&](int buf){
        #pragma unroll
        for (int s = 0; s < 2; s++){
            int f = tid + s*256; int r = f >> 5, c = (f & 31) * 4;
            *reinterpret_cast<float4*>(&Bs[buf][r][c]) = rb[s];
        }
    };

    ldA(0); ldB(0); stA(0); stB(0);
    __syncthreads();

    for (int kt = 0; kt < KT; kt++){
        int buf = kt & 1;
        if (kt + 1 < KT){ ldA(kt+1); ldB(kt+1); }
        #pragma unroll
        for (int kk = 0; kk < 16; kk++){
            float4 a0 = *reinterpret_cast<const float4*>(&As[buf][kk][ty*8]);
            float4 a1 = *reinterpret_cast<const float4*>(&As[buf][kk][ty*8 + 4]);
            const unsigned long long* bp =
                reinterpret_cast<const unsigned long long*>(&Bs[buf][kk][tx*8]);
            unsigned long long b0 = bp[0], b1 = bp[1], b2 = bp[2], b3 = bp[3];
            float av[8] = {a0.x, a0.y, a0.z, a0.w, a1.x, a1.y, a1.z, a1.w};
            #pragma unroll
            for (int i = 0; i < 8; i++){
                unsigned long long ap = pack2(av[i], av[i]);
                ffma2(acc[i][0], ap, b0);
                ffma2(acc[i][1], ap, b1);
                ffma2(acc[i][2], ap, b2);
                ffma2(acc[i][3], ap, b3);
            }
        }
        if (kt + 1 < KT){ stA(buf ^ 1); stB(buf ^ 1); __syncthreads(); }
    }

    int m0 = bm*128 + ty*8;
    int n0 = bn*128 + tx*8;
    float bv[8];
    #pragma unroll
    for (int j = 0; j < 8; j++) bv[j] = bias[n0 + j];

    if (EPI == 1){
        #pragma unroll
        for (int i = 0; i < 8; i++){
            float* crow = g_h + (size_t)(m0 + i) * DFFz + n0;
            #pragma unroll
            for (int j = 0; j < 4; j++){
                float2 v = unpack2(acc[i][j]);
                crow[2*j]   = gelu_exact(v.x + bv[2*j]);
                crow[2*j+1] = gelu_exact(v.y + bv[2*j+1]);
            }
        }
    } else {
        #pragma unroll
        for (int i = 0; i < 8; i++){
            int m = m0 + i;
            int bb = m >> 9;                 // KSEL = 512 rows per batch
            int t  = g_tokens[m];
            float w = g_rw[m];
            size_t base = ((size_t)bb * Ssz + t) * (size_t)Dd + n0;
            #pragma unroll
            for (int j = 0; j < 4; j++){
                float2 v = unpack2(acc[i][j]);
                out[base + 2*j]   = xin[base + 2*j]   + w * (v.x + bv[2*j]);
                out[base + 2*j+1] = xin[base + 2*j+1] + w * (v.y + bv[2*j+1]);
            }
        }
    }
}

// ---------------- launch -----------------------------------------------------
extern "C" void kernel_launch(void* const* d_in, const int* in_sizes, int n_in,
                              void* d_out, int out_size){
    const float* x  = (const float*)d_in[0];
    const float* Wr = (const float*)d_in[1];
    const float* br = (const float*)d_in[2];
    const float* W1 = (const float*)d_in[3];
    const float* b1 = (const float*)d_in[4];
    const float* W2 = (const float*)d_in[5];
    const float* b2 = (const float*)d_in[6];
    float* out = (float*)d_out;

    // pass-through copy of x into out (non-selected tokens unchanged)
    cudaMemcpyAsync(out, x, (size_t)Bb*Ssz*Dd*sizeof(float),
                    cudaMemcpyDeviceToDevice, 0);

    router_kernel<<<(Bb*Ssz)/8, 256>>>(x, Wr, br);
    topk_kernel<<<Bb, 1024>>>();
    gather_kernel<<<MROWS, 256>>>(x);
    gemm_kernel<1><<<dim3(DFFz/128, MROWS/128), 256>>>(W1, b1, nullptr, nullptr, DFFz, Dd);
    gemm_kernel<2><<<dim3(Dd/128,  MROWS/128), 256>>>(W2, b2, x, out, Dd, DFFz);
}